// round 6
// baseline (speedup 1.0000x reference)
#include <cuda_runtime.h>
#include <math.h>

// One WARP per row of 1024 floats (two [32,1024,1024] fp32 tensors).
// Two-phase, low-register variant:
//   Phase 1: sum the row with 8 LDG.128 (default .ca policy, values consumed
//            immediately -> registers die into the accumulator).
//   Phase 2: re-load the same 8 float4 (L1 hits: lines were just brought in
//            and per-SM streaming traffic in the interim is ~8KB vs 228KB L1),
//            scale by 1/degree, stream out with .cs.
// Phase-1 loads are inline asm so the compiler cannot CSE phase-2's reloads
// into phase-1 values (which would re-inflate register pressure).
// __launch_bounds__(256, 8) caps regs at 32 -> 64 warps/SM of memory
// parallelism. HBM traffic stays at the 1R+1W floor (re-read is L1-resident).
// Row ids [0,32768) -> adj0, [32768,65536) -> adj1; output is concatenated.

__device__ __forceinline__ float4 ldg_ca_v4(const float4* p)
{
    float4 r;
    asm volatile("ld.global.ca.v4.f32 {%0,%1,%2,%3}, [%4];"
                 : "=f"(r.x), "=f"(r.y), "=f"(r.z), "=f"(r.w)
                 : "l"(p));
    return r;
}

__global__ void __launch_bounds__(256, 8) row_norm_warp2p_kernel(
    const float* __restrict__ in0, const float* __restrict__ in1,
    float* __restrict__ out)
{
    const int wid = threadIdx.x >> 5;
    const int lid = threadIdx.x & 31;
    const long long gid = (long long)blockIdx.x * 8 + wid;   // 0 .. 65535
    const long long rows_per_tensor = 32768;

    const float* __restrict__ in = (gid < rows_per_tensor) ? in0 : in1;
    const long long row = gid & (rows_per_tensor - 1);

    const float4* __restrict__ inrow =
        reinterpret_cast<const float4*>(in + row * 1024);

    // ---- Phase 1: degree = row sum (values die into accumulator) ----
    float p[8];
    #pragma unroll
    for (int k = 0; k < 8; k++) {
        float4 t = ldg_ca_v4(&inrow[k * 32 + lid]);
        p[k] = (t.x + t.y) + (t.z + t.w);
    }
    float s = ((p[0] + p[1]) + (p[2] + p[3])) + ((p[4] + p[5]) + (p[6] + p[7]));

    // warp-only reduction (row sum broadcast to every lane)
    #pragma unroll
    for (int o = 16; o > 0; o >>= 1)
        s += __shfl_xor_sync(0xffffffffu, s, o);

    float inv = 1.0f / s;
    // reference semantics: zero out non-finite inverse (degree == 0 rows)
    if (!isfinite(inv)) inv = 0.0f;

    // ---- Phase 2: re-read (L1 hits), scale, stream out ----
    float4* __restrict__ outrow =
        reinterpret_cast<float4*>(out) + gid * 256;
    #pragma unroll
    for (int k = 0; k < 8; k++) {
        float4 t = inrow[k * 32 + lid];
        float4 o4;
        o4.x = t.x * inv;
        o4.y = t.y * inv;
        o4.z = t.z * inv;
        o4.w = t.w * inv;
        __stcs(&outrow[k * 32 + lid], o4);
    }
}

extern "C" void kernel_launch(void* const* d_in, const int* in_sizes, int n_in,
                              void* d_out, int out_size)
{
    const float* adj0 = (const float*)d_in[0];
    const float* adj1 = (const float*)d_in[1];
    float* out = (float*)d_out;

    // 65536 rows total, 8 rows (warps) per block
    row_norm_warp2p_kernel<<<8192, 256>>>(adj0, adj1, out);
}

// round 9
// speedup vs baseline: 1.1483x; 1.1483x over previous
#include <cuda_runtime.h>
#include <math.h>

// TWO warps per row of 1024 floats (two [32,1024,1024] fp32 tensors).
// Each lane holds 4 float4 (16 data regs) -> ~30 regs/thread total, so
// __launch_bounds__(256, 8) gives 8 CTAs/SM = 64 warps (full occupancy)
// while the row data stays register-resident between the degree reduction
// and the scaled store: HBM traffic = exactly 1R + 1W per element.
// Cross-warp combine: each warp's half-row sum goes through smem, one
// __syncthreads per block (8 warps -> cheap BAR).
// Block = 256 threads = 8 warps = 4 rows.
// Row ids [0,32768) -> adj0, [32768,65536) -> adj1; output is concatenated.

__global__ void __launch_bounds__(256, 8) row_norm_2w_kernel(
    const float* __restrict__ in0, const float* __restrict__ in1,
    float* __restrict__ out)
{
    const int wid  = threadIdx.x >> 5;     // 0..7
    const int lid  = threadIdx.x & 31;
    const int half = wid & 1;              // which half of the row
    const long long gid = (long long)blockIdx.x * 4 + (wid >> 1); // row id 0..65535
    const long long rows_per_tensor = 32768;

    const float* __restrict__ in = (gid < rows_per_tensor) ? in0 : in1;
    const long long row = gid & (rows_per_tensor - 1);

    // this warp's half-row: 512 floats = 128 float4, starting at half*128
    const float4* __restrict__ inhalf =
        reinterpret_cast<const float4*>(in + row * 1024) + half * 128;

    // 4 independent streaming loads per lane (MLP=4/thread)
    float4 v[4];
    #pragma unroll
    for (int k = 0; k < 4; k++)
        v[k] = __ldcs(&inhalf[k * 32 + lid]);

    float p[4];
    #pragma unroll
    for (int k = 0; k < 4; k++)
        p[k] = (v[k].x + v[k].y) + (v[k].z + v[k].w);
    float s = (p[0] + p[1]) + (p[2] + p[3]);

    // warp reduce -> half-row sum in every lane
    #pragma unroll
    for (int o = 16; o > 0; o >>= 1)
        s += __shfl_xor_sync(0xffffffffu, s, o);

    // cross-warp combine: one smem slot per warp, one block barrier
    __shared__ float halfsum[8];
    if (lid == 0) halfsum[wid] = s;
    __syncthreads();
    const float degree = halfsum[wid & ~1] + halfsum[wid | 1];

    float inv = 1.0f / degree;
    // reference semantics: zero out non-finite inverse (degree == 0 rows)
    if (!isfinite(inv)) inv = 0.0f;

    float4* __restrict__ outhalf =
        reinterpret_cast<float4*>(out) + gid * 256 + half * 128;
    #pragma unroll
    for (int k = 0; k < 4; k++) {
        float4 o4;
        o4.x = v[k].x * inv;
        o4.y = v[k].y * inv;
        o4.z = v[k].z * inv;
        o4.w = v[k].w * inv;
        __stcs(&outhalf[k * 32 + lid], o4);
    }
}

extern "C" void kernel_launch(void* const* d_in, const int* in_sizes, int n_in,
                              void* d_out, int out_size)
{
    const float* adj0 = (const float*)d_in[0];
    const float* adj1 = (const float*)d_in[1];
    float* out = (float*)d_out;

    // 65536 rows total, 4 rows per block (2 warps per row)
    row_norm_2w_kernel<<<16384, 256>>>(adj0, adj1, out);
}